// round 6
// baseline (speedup 1.0000x reference)
#include <cuda_runtime.h>
#include <cuda_bf16.h>
#include <cstdint>

// SkipGramMultiContext: B=16384, C_MAX=10, K_NEG=5, DIM=128, VOCAB=100000
// Output: float32[2] = {positive_loss, negative_loss}
//
// cp.async (LDGSTS) staging: register-free in-flight gathers into smem.
// Lane l copies bytes [16l, 16l+16) of each row and reads back exactly its
// own bytes -> no cross-thread smem dependency, wait_group 0 suffices.

#define B_SAMPLES 16384
#define C_MAX 10
#define K_NEG 5
#define DIM 128
#define NSCORE 15                      // 10 ctx + 5 neg
#define ROW_BYTES 512
#define ROWS 16                        // 15 score rows + target row
#define SAMPLE_BYTES (ROWS * ROW_BYTES)          // 8192
#define WARPS_PER_BLOCK 8
#define THREADS (WARPS_PER_BLOCK * 32)
#define SMEM_TOTAL (WARPS_PER_BLOCK * SAMPLE_BYTES)   // 65536

__device__ __forceinline__ uint32_t smem_u32(const void* p) {
    uint32_t a;
    asm("{ .reg .u64 t; cvta.to.shared.u64 t, %1; cvt.u32.u64 %0, t; }" : "=r"(a) : "l"(p));
    return a;
}

__device__ __forceinline__ void cp_async16(uint32_t dst, const void* src) {
    asm volatile("cp.async.cg.shared.global [%0], [%1], 16;" :: "r"(dst), "l"(src));
}

__device__ __forceinline__ void cp_async_commit_wait0() {
    asm volatile("cp.async.commit_group;");
    asm volatile("cp.async.wait_group 0;" ::: "memory");
}

__device__ __forceinline__ float neg_logsig(float x) {
    // -log(sigmoid(x)) = -min(x,0) + log(1 + exp(-|x|)); log arg in (1,2]
    return __logf(1.0f + __expf(-fabsf(x))) - fminf(x, 0.0f);
}

__device__ __forceinline__ float dot4(float4 a, float4 b) {
    return fmaf(a.x, b.x, fmaf(a.y, b.y, fmaf(a.z, b.z, a.w * b.w)));
}

__global__ void zero_out_kernel(float* out) {
    if (threadIdx.x < 2) out[threadIdx.x] = 0.0f;
}

__global__ __launch_bounds__(THREADS)
void skipgram_loss_kernel(const int* __restrict__ tw,
                          const int* __restrict__ cw,
                          const int* __restrict__ cl,
                          const int* __restrict__ nw,
                          const float* __restrict__ in_emb,
                          const float* __restrict__ out_emb,
                          float* __restrict__ out) {
    extern __shared__ char smem[];
    const int warp_id = (blockIdx.x * THREADS + threadIdx.x) >> 5;
    const int lane = threadIdx.x & 31;
    const int wib  = threadIdx.x >> 5;

    __shared__ float s_pos[WARPS_PER_BLOCK];
    __shared__ float s_neg[WARPS_PER_BLOCK];

    char* buf = smem + wib * SAMPLE_BYTES;
    const uint32_t dst_base = smem_u32(buf) + lane * 16;

    float pos_per = 0.0f, neg_per = 0.0f;

    if (warp_id < B_SAMPLES) {
        const int b = warp_id;

        // lanes 0..9 hold context indices, 10..14 negatives
        int idx = 0;
        if (lane < C_MAX)       idx = __ldg(&cw[b * C_MAX + lane]);
        else if (lane < NSCORE) idx = __ldg(&nw[b * K_NEG + (lane - C_MAX)]);
        const int len  = __ldg(&cl[b]);
        const int trow = __ldg(&tw[b]);

        // 16 register-free row gathers: each warp-wide cp.async covers one
        // 512B row (16B per lane). All 8KB in flight simultaneously.
        #pragma unroll
        for (int r = 0; r < NSCORE; r++) {
            const int row = __shfl_sync(0xffffffffu, idx, r);
            cp_async16(dst_base + r * ROW_BYTES,
                       out_emb + (size_t)row * DIM + lane * 4);
        }
        cp_async16(dst_base + NSCORE * ROW_BYTES,
                   in_emb + (size_t)trow * DIM + lane * 4);
        cp_async_commit_wait0();

        // dots from smem (each thread reads exactly the bytes it copied)
        const float4* row4 = reinterpret_cast<const float4*>(buf);
        const float4 t4 = row4[NSCORE * 32 + lane];
        float v[16];
        #pragma unroll
        for (int r = 0; r < NSCORE; r++)
            v[r] = dot4(t4, row4[r * 32 + lane]);
        v[15] = 0.0f;

        // Multi-value tree reduction: 16 lane-sums in 16 shuffles.
        // After the loop + o=1 finisher, lanes 2r/2r+1 hold the full sum of v[r].
        #pragma unroll
        for (int o = 16, nn = 8; o > 1; o >>= 1, nn >>= 1) {
            const bool up = (lane & o) != 0;
            #pragma unroll
            for (int i = 0; i < 8; i++) {
                if (i < nn) {
                    const float send = up ? v[i] : v[i + nn];
                    const float keep = up ? v[i + nn] : v[i];
                    v[i] = keep + __shfl_xor_sync(0xffffffffu, send, o);
                }
            }
        }
        v[0] += __shfl_xor_sync(0xffffffffu, v[0], 1);
        const float myscore = v[0];

        // even lane 2r evaluates score r
        float pv = 0.0f, nv = 0.0f;
        if ((lane & 1) == 0) {
            const int r = lane >> 1;
            if (r < C_MAX) {
                if (r < len) pv = neg_logsig(myscore);
            } else if (r < NSCORE) {
                nv = neg_logsig(-myscore);
            }
        }

        #pragma unroll
        for (int o = 16; o > 0; o >>= 1) {
            pv += __shfl_xor_sync(0xffffffffu, pv, o);
            nv += __shfl_xor_sync(0xffffffffu, nv, o);
        }

        if (len > 0) {
            pos_per = pv / (float)len;
            neg_per = nv * (1.0f / (float)K_NEG);
        }
    }

    if (lane == 0) {
        s_pos[wib] = pos_per;
        s_neg[wib] = neg_per;
    }
    __syncthreads();

    if (threadIdx.x == 0) {
        float ps = 0.0f, ns = 0.0f;
        #pragma unroll
        for (int w = 0; w < WARPS_PER_BLOCK; w++) { ps += s_pos[w]; ns += s_neg[w]; }
        const float invB = 1.0f / (float)B_SAMPLES;
        atomicAdd(&out[0], ps * invB);
        atomicAdd(&out[1], ns * invB);
    }
}

extern "C" void kernel_launch(void* const* d_in, const int* in_sizes, int n_in,
                              void* d_out, int out_size) {
    const int*   tw      = (const int*)d_in[0];
    const int*   cw      = (const int*)d_in[1];
    const int*   cl      = (const int*)d_in[2];
    const int*   nw      = (const int*)d_in[3];
    const float* in_emb  = (const float*)d_in[4];
    const float* out_emb = (const float*)d_in[5];
    float* out = (float*)d_out;

    zero_out_kernel<<<1, 32>>>(out);

    cudaFuncSetAttribute(skipgram_loss_kernel,
                         cudaFuncAttributeMaxDynamicSharedMemorySize, SMEM_TOTAL);
    const int num_blocks = B_SAMPLES / WARPS_PER_BLOCK;
    skipgram_loss_kernel<<<num_blocks, THREADS, SMEM_TOTAL>>>(
        tw, cw, cl, nw, in_emb, out_emb, out);
}

// round 7
// speedup vs baseline: 1.2224x; 1.2224x over previous
#include <cuda_runtime.h>
#include <cuda_bf16.h>
#include <cstdint>

// SkipGramMultiContext: B=16384, C_MAX=10, K_NEG=5, DIM=128, VOCAB=100000
// Output: float32[2] = {positive_loss, negative_loss}
//
// Half-warp-per-sample: lanes 0-15 = sample A, lanes 16-31 = sample B.
// Each lane covers 32B (two float4 chunks) of every 512B row. One shared
// v[16] register array and ONE width-16 tree reduction (15 SHFL) serve
// both samples at once; 40 SHFL per 2 samples vs 74 before.

#define B_SAMPLES 16384
#define C_MAX 10
#define K_NEG 5
#define DIM 128
#define NSCORE 15
#define WARPS_PER_BLOCK 8
#define THREADS (WARPS_PER_BLOCK * 32)
#define NWARPS (B_SAMPLES / 2)

__device__ __forceinline__ float neg_logsig(float x) {
    // -log(sigmoid(x)) = -min(x,0) + log(1 + exp(-|x|)); log arg in (1,2]
    return __logf(1.0f + __expf(-fabsf(x))) - fminf(x, 0.0f);
}

__device__ __forceinline__ float dot4(float4 a, float4 b) {
    return fmaf(a.x, b.x, fmaf(a.y, b.y, fmaf(a.z, b.z, a.w * b.w)));
}

__global__ void zero_out_kernel(float* out) {
    if (threadIdx.x < 2) out[threadIdx.x] = 0.0f;
}

__global__ __launch_bounds__(THREADS)
void skipgram_loss_kernel(const int* __restrict__ tw,
                          const int* __restrict__ cw,
                          const int* __restrict__ cl,
                          const int* __restrict__ nw,
                          const float* __restrict__ in_emb,
                          const float* __restrict__ out_emb,
                          float* __restrict__ out) {
    const int w     = (blockIdx.x * THREADS + threadIdx.x) >> 5;
    const int lane  = threadIdx.x & 31;
    const int h     = lane >> 4;       // 0 = sample A, 1 = sample B
    const int hlane = lane & 15;
    const int wib   = threadIdx.x >> 5;

    __shared__ float s_pos[WARPS_PER_BLOCK];
    __shared__ float s_neg[WARPS_PER_BLOCK];

    const int b = 2 * w + h;           // this half-warp's sample

    // per-half indices: hlane 0..9 ctx, 10..14 neg
    int idx = 0;
    if (hlane < C_MAX)       idx = __ldg(&cw[b * C_MAX + hlane]);
    else if (hlane < NSCORE) idx = __ldg(&nw[b * K_NEG + (hlane - C_MAX)]);
    const int len = __ldg(&cl[b]);

    // target row: lane covers float4 chunks hlane and 16+hlane of its row
    const int trow = __ldg(&tw[b]);
    const float4* trow4 = reinterpret_cast<const float4*>(in_emb + (size_t)trow * DIM);
    const float4 t0 = trow4[hlane];
    const float4 t1 = trow4[16 + hlane];

    // 15 row-pairs: each LDG.128 covers 256B of A's row + 256B of B's row
    float v[16];
    #pragma unroll
    for (int r = 0; r < NSCORE; r++) {
        const int row = __shfl_sync(0xffffffffu, idx, (h << 4) + r);
        const float4* c4 = reinterpret_cast<const float4*>(out_emb + (size_t)row * DIM);
        const float4 c0 = c4[hlane];
        const float4 c1 = c4[16 + hlane];
        v[r] = dot4(t0, c0) + dot4(t1, c1);
    }
    v[15] = 0.0f;

    // Width-16 multi-value tree: offsets 8,4,2,1. XOR partners stay within
    // each half. After the tree, lane (h*16 + r) holds the FULL 16-lane sum
    // of v[r] for its sample (bit k of r comes from lane bit k at step o=2^k).
    #pragma unroll
    for (int o = 8, nn = 8; o > 0; o >>= 1, nn >>= 1) {
        const bool up = (lane & o) != 0;
        #pragma unroll
        for (int i = 0; i < 8; i++) {
            if (i < nn) {
                const float send = up ? v[i] : v[i + nn];
                const float keep = up ? v[i + nn] : v[i];
                v[i] = keep + __shfl_xor_sync(0xffffffffu, send, o);
            }
        }
    }
    const float score = v[0];          // lane holds score index r = hlane

    // per-lane contribution, pre-normalized per sample
    float pv = 0.0f, nv = 0.0f;
    if (hlane < C_MAX) {
        if (hlane < len) pv = neg_logsig(score) / (float)len;   // len >= 1 here
    } else if (hlane < NSCORE) {
        if (len > 0) nv = neg_logsig(-score) * (1.0f / (float)K_NEG);
    }

    // butterfly within half (8,4,2,1) then merge halves (16)
    #pragma unroll
    for (int o = 8; o > 0; o >>= 1) {
        pv += __shfl_xor_sync(0xffffffffu, pv, o);
        nv += __shfl_xor_sync(0xffffffffu, nv, o);
    }
    pv += __shfl_xor_sync(0xffffffffu, pv, 16);
    nv += __shfl_xor_sync(0xffffffffu, nv, 16);

    if (lane == 0) {
        s_pos[wib] = pv;
        s_neg[wib] = nv;
    }
    __syncthreads();

    if (threadIdx.x == 0) {
        float ps = 0.0f, ns = 0.0f;
        #pragma unroll
        for (int ww = 0; ww < WARPS_PER_BLOCK; ww++) { ps += s_pos[ww]; ns += s_neg[ww]; }
        const float invB = 1.0f / (float)B_SAMPLES;
        atomicAdd(&out[0], ps * invB);
        atomicAdd(&out[1], ns * invB);
    }
}

extern "C" void kernel_launch(void* const* d_in, const int* in_sizes, int n_in,
                              void* d_out, int out_size) {
    const int*   tw      = (const int*)d_in[0];
    const int*   cw      = (const int*)d_in[1];
    const int*   cl      = (const int*)d_in[2];
    const int*   nw      = (const int*)d_in[3];
    const float* in_emb  = (const float*)d_in[4];
    const float* out_emb = (const float*)d_in[5];
    float* out = (float*)d_out;

    zero_out_kernel<<<1, 32>>>(out);

    const int num_blocks = NWARPS / WARPS_PER_BLOCK;   // 1024
    skipgram_loss_kernel<<<num_blocks, THREADS>>>(tw, cw, cl, nw, in_emb, out_emb, out);
}